// round 4
// baseline (speedup 1.0000x reference)
#include <cuda_runtime.h>
#include <math.h>

// ACT_R activation recurrence.
// sp: [S=512, B=256, 1] f32 (sorted along S).  w: [a, c, s, tau, h].
// out: [S-1, B, 1] f32.
//
// Column-swept formulation:
//   E_i = sum_{j<i} max(sc_i - sc_j, 1)^{p_j},  p_j = -(c*E_j + a),  E_0 = 0
//   out[i-1] = 1 / (1 + exp((tau - log(E_i)) / s))
// One block per batch element, one thread per row. p_j published via
// NaN-sentinel in shared memory (single 32-bit word => atomic publish).
// Each warp's own 32-row diagonal block is handled in-warp via shfl.

#define S_LEN 512
#define BATCH 256

__device__ __forceinline__ float ex2f(float x) {
    float y; asm("ex2.approx.ftz.f32 %0, %1;" : "=f"(y) : "f"(x)); return y;
}
__device__ __forceinline__ float lg2f(float x) {
    float y; asm("lg2.approx.ftz.f32 %0, %1;" : "=f"(y) : "f"(x)); return y;
}

__global__ void __launch_bounds__(S_LEN, 2)
actr_kernel(const float* __restrict__ sp, const float* __restrict__ w,
            float* __restrict__ out) {
    __shared__ float sc[S_LEN];     // scaled timestamps for this batch element
    __shared__ float psm[S_LEN];    // published exponents p_j (NaN = not ready)

    const int b    = blockIdx.x;
    const int t    = threadIdx.x;          // row index
    const int lane = t & 31;
    const int base = t & ~31;              // this warp's diagonal base row

    const float a   = w[0];
    const float c   = w[1];
    const float s   = w[2];
    const float tau = w[3];
    const float h   = w[4];
    const float scale = 86400.0f * h;

    const float my_sc = sp[t * BATCH + b] * scale;
    sc[t]  = my_sc;
    psm[t] = __int_as_float(0x7fc00000);   // NaN sentinel
    __syncthreads();

    volatile float* vp = psm;
    float acc = 0.0f;                      // E_t accumulator (thread-private)

    // ---- off-diagonal columns j = 0 .. base-1 (warp-uniform) ----
    for (int j = 0; j < base; j += 4) {
        // Poll the LAST column of the group; columns publish strictly in
        // order, so j..j+2 are ready once j+3 is. Then read the group
        // (reads issue after the successful poll in warp program order).
        float p3 = vp[j + 3];
        while (__isnanf(p3)) { __nanosleep(40); p3 = vp[j + 3]; }
        asm volatile("" ::: "memory");     // keep group reads below the poll
        float p0 = vp[j + 0];
        float p1 = vp[j + 1];
        float p2 = vp[j + 2];
        float d0 = fmaxf(my_sc - sc[j + 0], 1.0f);
        float d1 = fmaxf(my_sc - sc[j + 1], 1.0f);
        float d2 = fmaxf(my_sc - sc[j + 2], 1.0f);
        float d3 = fmaxf(my_sc - sc[j + 3], 1.0f);
        acc += ex2f(p0 * lg2f(d0));
        acc += ex2f(p1 * lg2f(d1));
        acc += ex2f(p2 * lg2f(d2));
        acc += ex2f(p3 * lg2f(d3));
    }

    // ---- diagonal block: columns base .. base+30, in-warp via shfl ----
    float p_mine = 0.0f;
    #pragma unroll 1
    for (int k = 0; k < 32; ++k) {
        if (lane == k) {
            // Row base+k's accumulator is complete (columns 0..base+k-1).
            p_mine = -fmaf(c, acc, a);
            vp[base + k] = p_mine;         // publish for later warps
        }
        float pj = __shfl_sync(0xffffffffu, p_mine, k);
        if (lane > k) {
            float d = fmaxf(my_sc - sc[base + k], 1.0f);
            acc += ex2f(pj * lg2f(d));
        }
    }

    // ---- output: rows 1..S-1 ----
    if (t >= 1) {
        float m   = logf(acc);
        float act = 1.0f / (1.0f + expf((tau - m) / s));
        out[(t - 1) * BATCH + b] = act;
    }
}

extern "C" void kernel_launch(void* const* d_in, const int* in_sizes, int n_in,
                              void* d_out, int out_size) {
    const float* sp = (const float*)d_in[0];
    const float* w  = (const float*)d_in[1];
    float* out      = (float*)d_out;
    (void)in_sizes; (void)n_in; (void)out_size;
    actr_kernel<<<BATCH, S_LEN>>>(sp, w, out);
}